// round 13
// baseline (speedup 1.0000x reference)
#include <cuda_runtime.h>
#include <math.h>

#define NN 16800
#define KK 1024
#define BB 64
#define NT 1024
#define HP 257
#define SLICES1 2
#define SL1 (NN / SLICES1)   // 8400
#define SLICES2 4
#define SL2 (NN / SLICES2)   // 4200

// ---- device-global scratch (allocation-free workaround) ----
__device__ unsigned            g_okey[BB * NN];
__device__ unsigned long long  g_cand[BB * KK];
__device__ unsigned long long  g_surv[(size_t)BB * NN];
struct Cnt { unsigned hist[BB][256]; int cntg[BB]; int cnts[BB]; };
__device__ Cnt g_c;

// exact-equivalent IoU>0.3 test (bit-identical decisions to __fdiv_rn(...)>0.3f)
__device__ __forceinline__ bool iou_gt(float inter, float den) {
    if (inter > 0.301f * den) return true;
    if (inter > 0.299f * den) return __fdiv_rn(inter, den) > 0.3f;
    return false;
}

// ================= K1: okeys + per-image 256-bucket histogram =================
__global__ __launch_bounds__(NT, 1)
void k_hist(const float* __restrict__ p_conf)
{
    __shared__ unsigned hist32[32 * HP];
    const int b = blockIdx.y, sl = blockIdx.x, tid = threadIdx.x;
    const int lane = tid & 31, wrp = tid >> 5;
    const float* conf = p_conf + (size_t)b * NN;

    for (int t = tid; t < 32 * HP; t += NT) hist32[t] = 0u;
    __syncthreads();

    const int base0 = sl * SL1;
    #pragma unroll 1
    for (int it = 0; it < (SL1 + NT - 1) / NT; it++) {
        int i = base0 + it * NT + tid;
        bool v = (i < base0 + SL1);
        unsigned ok = 0u;
        if (v) {
            float c = conf[i];
            ok = (c >= 0.0f) ? (__float_as_uint(c) | 0x80000000u) : 0u;
            g_okey[b * NN + i] = ok;
        }
        unsigned bucket = v ? (ok >> 24) : 0xFFFFFFFFu;
        unsigned grp = __match_any_sync(0xffffffffu, bucket);
        if (v && lane == (__ffs(grp) - 1))
            hist32[wrp * HP + bucket] += (unsigned)__popc(grp);
    }
    __syncthreads();
    if (tid < 256) {
        unsigned c = 0;
        #pragma unroll
        for (int w = 0; w < 32; w++) c += hist32[w * HP + tid];
        if (c) atomicAdd(&g_c.hist[b][tid], c);
    }
}

// ================= K2: compact >d0 -> g_cand, ==d0 -> g_surv =================
__global__ __launch_bounds__(NT, 1)
void k_compact()
{
    __shared__ unsigned hist[256];
    __shared__ unsigned warpsum[8];
    __shared__ unsigned s_d0;
    const int b = blockIdx.y, sl = blockIdx.x, tid = threadIdx.x;
    const int lane = tid & 31, wrp = tid >> 5;

    if (tid < 256) hist[tid] = g_c.hist[b][tid];
    __syncthreads();

    unsigned cnt = 0, ssum = 0;
    if (tid < 256) {
        cnt = hist[tid];
        ssum = cnt;
        #pragma unroll
        for (int d = 1; d < 32; d <<= 1) {
            unsigned x = __shfl_down_sync(0xffffffffu, ssum, d);
            if (lane + d < 32) ssum += x;
        }
        if (lane == 0) warpsum[wrp] = ssum;
    }
    __syncthreads();
    if (tid < 256) {
        unsigned hi = 0;
        for (int w = wrp + 1; w < 8; w++) hi += warpsum[w];
        unsigned S = ssum + hi;
        if (S >= (unsigned)KK && S - cnt < (unsigned)KK) s_d0 = (unsigned)tid;
    }
    __syncthreads();
    const unsigned d0 = s_d0;

    const int base0 = sl * SL2;
    #pragma unroll 1
    for (int it = 0; it < (SL2 + NT - 1) / NT; it++) {
        int i = base0 + it * NT + tid;
        bool v = (i < base0 + SL2);
        unsigned ok = v ? g_okey[b * NN + i] : 0u;
        bool gt = v && ((ok >> 24) > d0);
        bool eq = v && ((ok >> 24) == d0);
        unsigned balg = __ballot_sync(0xffffffffu, gt);
        int pg = 0;
        if (lane == 0 && balg) pg = atomicAdd(&g_c.cntg[b], __popc(balg));
        pg = __shfl_sync(0xffffffffu, pg, 0);
        if (gt) g_cand[b * KK + pg + __popc(balg & ((1u << lane) - 1u))] =
                    (((unsigned long long)ok) << 32) | (unsigned)(~(unsigned)i);
        unsigned bale = __ballot_sync(0xffffffffu, eq);
        int pe = 0;
        if (lane == 0 && bale) pe = atomicAdd(&g_c.cnts[b], __popc(bale));
        pe = __shfl_sync(0xffffffffu, pe, 0);
        if (eq) g_surv[(size_t)b * NN + pe + __popc(bale & ((1u << lane) - 1u))] =
                    (((unsigned long long)ok) << 32) | (unsigned)(~(unsigned)i);
    }
}

// ================= K3: survivor radix + sort + decode + NMS + output =================
struct S3 {
    float4 sbox[KK];
    float  sarea[KK];
    float  sval[KK];
    float  smult[KK];
    unsigned long long smask[KK];
    float  skpt[KK * 10];
    unsigned long long cand[KK];
    unsigned long long s_kept;
    unsigned hist[256];
    unsigned warpsum[8];
    unsigned pref_arr[5];
    int kr_arr[5];
    int wsum[32];
    int cnt;
    int eqtot;
};

__global__ __launch_bounds__(NT, 1)
void k_nms(const float* __restrict__ p_loc,
           const float* __restrict__ p_landms,
           const float* __restrict__ anchors,
           float* __restrict__ out)
{
    extern __shared__ char raw[];
    S3* s = reinterpret_cast<S3*>(raw);
    const int b = blockIdx.x, tid = threadIdx.x;
    const int lane = tid & 31, wrp = tid >> 5;

    if (tid < 256) s->hist[tid] = g_c.hist[b][tid];
    __syncthreads();

    // ---- digit find pass 0 (from histogram) ----
    {
        unsigned cnt = 0, ssum = 0;
        if (tid < 256) {
            cnt = s->hist[tid];
            ssum = cnt;
            #pragma unroll
            for (int d = 1; d < 32; d <<= 1) {
                unsigned x = __shfl_down_sync(0xffffffffu, ssum, d);
                if (lane + d < 32) ssum += x;
            }
            if (lane == 0) s->warpsum[wrp] = ssum;
        }
        __syncthreads();
        if (tid < 256) {
            unsigned hi = 0;
            for (int w = wrp + 1; w < 8; w++) hi += s->warpsum[w];
            unsigned S = ssum + hi;
            if (S >= (unsigned)KK && S - cnt < (unsigned)KK) {
                s->pref_arr[1] = (unsigned)tid;
                s->kr_arr[1] = KK - (int)(S - cnt);
                s->eqtot = (int)cnt;
            }
        }
        __syncthreads();
    }
    const int cg = KK - s->kr_arr[1];   // count of > d0 items
    const int sv = s->eqtot;            // count of == d0 items

    // stage gt candidates into smem
    for (int t = tid; t < cg; t += NT) s->cand[t] = g_cand[b * KK + t];

    // ---- passes 1..3 over g_surv ----
    const int iters = (sv + NT - 1) / NT;
    for (int p = 1; p < 4; p++) {
        const int shift = 24 - 8 * p;
        if (tid < 256) s->hist[tid] = 0u;
        __syncthreads();
        const unsigned prefv = s->pref_arr[p];
        const int krloc = s->kr_arr[p];
        for (int it = 0; it < iters; it++) {
            int ix = it * NT + tid;
            bool valid = (ix < sv);
            unsigned key = valid ? (unsigned)(g_surv[(size_t)b * NN + ix] >> 32) : 0u;
            bool part = valid && ((key >> (shift + 8)) == prefv);
            unsigned bucket = part ? ((key >> shift) & 255u) : 0xFFFFFFFFu;
            unsigned grp = __match_any_sync(0xffffffffu, bucket);
            if (part && lane == (__ffs(grp) - 1))
                atomicAdd(&s->hist[bucket], (unsigned)__popc(grp));
        }
        __syncthreads();
        unsigned cnt = 0, ssum = 0;
        if (tid < 256) {
            cnt = s->hist[tid];
            ssum = cnt;
            #pragma unroll
            for (int d = 1; d < 32; d <<= 1) {
                unsigned x = __shfl_down_sync(0xffffffffu, ssum, d);
                if (lane + d < 32) ssum += x;
            }
            if (lane == 0) s->warpsum[wrp] = ssum;
        }
        __syncthreads();
        if (tid < 256) {
            unsigned hi = 0;
            for (int w = wrp + 1; w < 8; w++) hi += s->warpsum[w];
            unsigned S = ssum + hi;
            if (S >= (unsigned)krloc && S - cnt < (unsigned)krloc) {
                s->pref_arr[p + 1] = (prefv << 8) | (unsigned)tid;
                s->kr_arr[p + 1] = krloc - (int)(S - cnt);
                s->eqtot = (int)cnt;
            }
        }
        __syncthreads();
    }

    // ---- final compaction ----
    if (s->eqtot == s->kr_arr[4]) {          // fastpath (typical)
        const unsigned T = s->pref_arr[4];
        if (tid == 0) s->cnt = cg;
        __syncthreads();
        for (int it = 0; it < iters; it++) {
            int ix = it * NT + tid;
            bool valid = (ix < sv);
            unsigned long long e = valid ? g_surv[(size_t)b * NN + ix] : 0ull;
            bool take = valid && ((unsigned)(e >> 32) >= T);
            unsigned bal = __ballot_sync(0xffffffffu, take);
            int pg = 0;
            if (lane == 0 && bal) pg = atomicAdd(&s->cnt, __popc(bal));
            pg = __shfl_sync(0xffffffffu, pg, 0);
            if (take) s->cand[pg + __popc(bal & ((1u << lane) - 1u))] = e;
        }
        __syncthreads();
    } else {                                  // rare stable fallback: rescan g_okey
        const unsigned T = s->pref_arr[4];
        const int need = s->kr_arr[4];
        const int eq0 = KK - need;
        if (tid == 0) s->cnt = 0;
        __syncthreads();
        int eqbase = 0;
        for (int base = 0; base < NN; base += NT) {
            int i = base + tid;
            bool v = (i < NN);
            unsigned ok = v ? g_okey[b * NN + i] : 0u;
            bool gt = v && (ok > T);
            bool eq = v && (ok == T);
            if (gt) {
                int p2 = atomicAdd(&s->cnt, 1);
                s->cand[p2] = (((unsigned long long)ok) << 32) | (unsigned)(~(unsigned)i);
            }
            unsigned bal = __ballot_sync(0xffffffffu, eq);
            if (lane == 0) s->wsum[wrp] = __popc(bal);
            __syncthreads();
            int woff = 0, tot = 0;
            #pragma unroll
            for (int w = 0; w < 32; w++) { int x = s->wsum[w]; if (w < wrp) woff += x; tot += x; }
            int rank = eqbase + woff + __popc(bal & ((1u << lane) - 1u));
            if (eq && rank < need)
                s->cand[eq0 + rank] = (((unsigned long long)T) << 32) | (unsigned)(~(unsigned)i);
            eqbase += tot;
            __syncthreads();
        }
    }

    // ---- bitonic sort descending; warp-local shfl phases for j<=16 ----
    {
        unsigned long long v = s->cand[tid];
        #pragma unroll
        for (int k2 = 2; k2 <= 32; k2 <<= 1) {
            #pragma unroll
            for (int j = k2 >> 1; j >= 1; j >>= 1) {
                unsigned long long pv = __shfl_xor_sync(0xffffffffu, v, j);
                bool keepMax = ((tid & k2) == 0) == ((tid & j) == 0);
                v = keepMax ? (v > pv ? v : pv) : (v < pv ? v : pv);
            }
        }
        s->cand[tid] = v;
    }
    __syncthreads();
    for (int k2 = 64; k2 <= KK; k2 <<= 1) {
        for (int j = k2 >> 1; j >= 32; j >>= 1) {
            int ixj = tid ^ j;
            if (ixj > tid) {
                unsigned long long a = s->cand[tid], cc = s->cand[ixj];
                bool sw = ((tid & k2) == 0) ? (a < cc) : (a > cc);
                if (sw) { s->cand[tid] = cc; s->cand[ixj] = a; }
            }
            __syncthreads();
        }
        unsigned long long v = s->cand[tid];
        #pragma unroll
        for (int j = 16; j >= 1; j >>= 1) {
            unsigned long long pv = __shfl_xor_sync(0xffffffffu, v, j);
            bool keepMax = ((tid & k2) == 0) == ((tid & j) == 0);
            v = keepMax ? (v > pv ? v : pv) : (v < pv ? v : pv);
        }
        s->cand[tid] = v;
        __syncthreads();
    }

    // ---- gather + decode into smem ----
    float4 bj; float aj;
    {
        int t = tid;
        unsigned long long cd = s->cand[t];
        int idx = (int)(~(unsigned)cd);
        unsigned ok = (unsigned)(cd >> 32);
        float c = __uint_as_float(ok & 0x7FFFFFFFu);
        float vj = (ok != 0u) ? (1.0f / (1.0f + expf(-c))) : -1.0f;
        float4 a = ((const float4*)anchors)[idx];
        float4 l = ((const float4*)p_loc)[(size_t)b * NN + idx];
        float cx = a.x + l.x * 0.1f * a.z;
        float cy = a.y + l.y * 0.1f * a.w;
        float w = a.z * expf(l.z * 0.2f);
        float h = a.w * expf(l.w * 0.2f);
        float x1 = cx - w * 0.5f, y1 = cy - h * 0.5f;
        float x2 = cx + w * 0.5f, y2 = cy + h * 0.5f;
        bj = make_float4(x1, y1, x2, y2);
        aj = fmaxf(x2 - x1, 0.0f) * fmaxf(y2 - y1, 0.0f);
        s->sbox[t] = bj;
        s->sarea[t] = aj;
        s->sval[t] = vj;
        s->smult[t] = (ok != 0u) ? 1.0f : 0.0f;
        const float2* lm2 = (const float2*)(p_landms + ((size_t)b * NN + idx) * 10);
        #pragma unroll
        for (int p2 = 0; p2 < 5; p2++) {
            float2 d = lm2[p2];
            s->skpt[t * 10 + 2 * p2]     = a.x + d.x * 0.1f * a.z;
            s->skpt[t * 10 + 2 * p2 + 1] = a.y + d.y * 0.1f * a.w;
        }
    }
    __syncthreads();

    // ---- Phase A: intra-chunk 64x64 suppression masks ----
    {
        int t64 = tid & 63, base = tid & ~63;
        unsigned long long m = 0ull;
        for (int j = t64 + 1; j < 64; j++) {
            float4 bq = s->sbox[base + j];
            float  aq = s->sarea[base + j];
            float lx = fmaxf(bj.x, bq.x);
            float ly = fmaxf(bj.y, bq.y);
            float rx = fminf(bj.z, bq.z);
            float ry = fminf(bj.w, bq.w);
            float ww = fmaxf(rx - lx, 0.0f);
            float hh = fmaxf(ry - ly, 0.0f);
            if (ww > 0.0f && hh > 0.0f) {
                float inter = ww * hh;
                float den = aj + aq - inter + 1e-9f;
                if (iou_gt(inter, den)) m |= (1ull << j);
            }
        }
        s->smask[tid] = m;
    }
    __syncthreads();

    // ---- Phase B: 16 sequential chunks (barrier version — proven) ----
    #pragma unroll 1
    for (int c = 0; c < 16; c++) {
        if (tid < 32) {   // warp 0: ffs-skip scan (steps only on kept rows)
            int r0 = c * 64 + tid, r1 = r0 + 32;
            unsigned blo = __ballot_sync(0xffffffffu, s->smult[r0] != 0.0f);
            unsigned bhi = __ballot_sync(0xffffffffu, s->smult[r1] != 0.0f);
            unsigned long long a = (unsigned long long)blo | ((unsigned long long)bhi << 32);
            unsigned long long mlo = s->smask[r0];
            unsigned long long mhi = s->smask[r1];
            unsigned long long kept = 0ull;
            while (a) {
                int t = __ffsll((long long)a) - 1;
                kept |= (1ull << t);
                unsigned long long mrow = (t < 32)
                    ? __shfl_sync(0xffffffffu, mlo, t)
                    : __shfl_sync(0xffffffffu, mhi, t - 32);
                a &= ~(mrow | (1ull << t));
            }
            s->smult[r0] = ((kept >> tid) & 1ull) ? 1.0f : 0.0f;
            s->smult[r1] = ((kept >> (tid + 32)) & 1ull) ? 1.0f : 0.0f;
            if (tid == 0) s->s_kept = kept;
        }
        __syncthreads();
        if (tid >= (c + 1) * 64 && s->smult[tid] != 0.0f) {
            unsigned long long k = s->s_kept;
            while (k) {
                int t = __ffsll((long long)k) - 1;
                k &= k - 1;
                int pi = c * 64 + t;
                float4 bi = s->sbox[pi];
                float  ai = s->sarea[pi];
                float lx = fmaxf(bi.x, bj.x);
                float ly = fmaxf(bi.y, bj.y);
                float rx = fminf(bi.z, bj.z);
                float ry = fminf(bi.w, bj.w);
                float ww = fmaxf(rx - lx, 0.0f);
                float hh = fmaxf(ry - ly, 0.0f);
                if (ww > 0.0f && hh > 0.0f) {
                    float inter = ww * hh;
                    float den = ai + aj - inter + 1e-9f;
                    if (iou_gt(inter, den)) { s->smult[tid] = 0.0f; break; }
                }
            }
        }
        __syncthreads();
    }

    // ---- masked output: [ltrb(4) | kpts(10) | score(1)] * keep, float4 stores ----
    float4* out4 = (float4*)(out + (size_t)b * KK * 15);
    for (int e4 = tid; e4 < (KK * 15) / 4; e4 += NT) {
        float r[4];
        #pragma unroll
        for (int q = 0; q < 4; q++) {
            int e = e4 * 4 + q;
            int row = e / 15;
            int c2 = e - row * 15;
            float m = s->smult[row];
            float v;
            if (c2 < 4)       v = ((const float*)&s->sbox[row])[c2];
            else if (c2 < 14) v = s->skpt[row * 10 + (c2 - 4)];
            else              v = s->sval[row];
            r[q] = v * m;
        }
        out4[e4] = make_float4(r[0], r[1], r[2], r[3]);
    }
}

extern "C" void kernel_launch(void* const* d_in, const int* in_sizes, int n_in,
                              void* d_out, int out_size) {
    const float* p_loc    = (const float*)d_in[0];
    const float* p_conf   = (const float*)d_in[1];
    const float* p_landms = (const float*)d_in[2];
    const float* anchors  = (const float*)d_in[3];

    void* cptr = nullptr;
    cudaGetSymbolAddress(&cptr, g_c);
    cudaMemsetAsync(cptr, 0, sizeof(Cnt));

    cudaFuncSetAttribute(k_nms, cudaFuncAttributeMaxDynamicSharedMemorySize, (int)sizeof(S3));

    k_hist<<<dim3(SLICES1, BB), NT>>>(p_conf);
    k_compact<<<dim3(SLICES2, BB), NT>>>();
    k_nms<<<BB, NT, sizeof(S3)>>>(p_loc, p_landms, anchors, (float*)d_out);
}

// round 16
// speedup vs baseline: 1.2481x; 1.2481x over previous
#include <cuda_runtime.h>
#include <math.h>

#define NN 16800
#define KK 1024
#define BB 64
#define NT 1024
#define HP 257
#define SVMAX 6144

struct SF {
    union {
        struct {                              // select phase
            unsigned okey[NN];                // 67200 B
            unsigned hist32[32 * HP];         // 32896 B
            unsigned long long surv[SVMAX];   // 49152 B
            unsigned hist256[256];
        } a;
        struct {                              // nms phase
            float4 sbox[KK];
            float  sarea[KK];
            float  sval[KK];
            unsigned long long smask[KK];     // intra-chunk row masks
            float  skpt[KK * 10];
        } n;
    } u;
    unsigned long long cand[KK];
    unsigned long long skept[16];
    unsigned salive[32];
    int ready[16];
    int pub;
    unsigned warpsum[8];
    unsigned pref_arr[5];
    int kr_arr[5];
    int wsum[32];
    int cntgt;
    int svcnt;
    int eqtot;
};

// Suppression test, bit-identical to __fdiv_rn(inter, ((ai+aj)-inter)+1e-9f) > 0.3f.
// ajp = aj + 1e-9f precomputed; cheap band tests tolerate the reassociated den
// (band margin 0.33% >> ulp noise); exact path recomputes den in reference order.
__device__ __forceinline__ bool iou_sup(float inter, float ai, float aj, float ajp) {
    float den = ai + ajp - inter;
    if (inter > 0.301f * den) return true;
    if (inter > 0.299f * den) {
        float dex = ai + aj - inter + 1e-9f;
        return __fdiv_rn(inter, dex) > 0.3f;
    }
    return false;
}

__global__ __launch_bounds__(NT, 1)
void k_fused(const float* __restrict__ p_loc,
             const float* __restrict__ p_conf,
             const float* __restrict__ p_landms,
             const float* __restrict__ anchors,
             float* __restrict__ out)
{
    extern __shared__ char raw[];
    SF* s = reinterpret_cast<SF*>(raw);
    const int b = blockIdx.x, tid = threadIdx.x;
    const int lane = tid & 31, wrp = tid >> 5;
    const float* conf = p_conf + (size_t)b * NN;

    if (tid == 0) { s->pref_arr[0] = 0u; s->kr_arr[0] = KK; s->cntgt = 0; s->svcnt = 0; s->eqtot = 0; s->pub = 0; }
    if (tid < 16) s->ready[tid] = 0;

    // ================= pass 0: 8-bit top byte, per-warp histograms =================
    for (int t = tid; t < 32 * HP; t += NT) s->u.a.hist32[t] = 0u;
    __syncthreads();
    for (int base = 0; base < NN; base += NT) {
        int i = base + tid;
        bool v = (i < NN);
        unsigned ok = 0u;
        if (v) {
            float c = conf[i];
            ok = (c >= 0.0f) ? (__float_as_uint(c) | 0x80000000u) : 0u;
            s->u.a.okey[i] = ok;
        }
        unsigned bucket = v ? (ok >> 24) : 0xFFFFFFFFu;
        unsigned grp = __match_any_sync(0xffffffffu, bucket);
        if (v && lane == (__ffs(grp) - 1))
            s->u.a.hist32[wrp * HP + bucket] += (unsigned)__popc(grp);
    }
    __syncthreads();
    {   // digit find (threads 0..255 own buckets)
        unsigned cnt = 0, ssum = 0;
        if (tid < 256) {
            #pragma unroll
            for (int w = 0; w < 32; w++) cnt += s->u.a.hist32[w * HP + tid];
            ssum = cnt;
            #pragma unroll
            for (int d = 1; d < 32; d <<= 1) {
                unsigned x = __shfl_down_sync(0xffffffffu, ssum, d);
                if (lane + d < 32) ssum += x;
            }
            if (lane == 0) s->warpsum[wrp] = ssum;
        }
        __syncthreads();
        if (tid < 256) {
            unsigned hi = 0;
            for (int w = wrp + 1; w < 8; w++) hi += s->warpsum[w];
            unsigned S = ssum + hi;
            if (S >= (unsigned)KK && S - cnt < (unsigned)KK) {
                s->pref_arr[1] = (unsigned)tid;
                s->kr_arr[1] = KK - (int)(S - cnt);
                s->eqtot = (int)cnt;
            }
        }
        __syncthreads();
    }

    const int E0 = s->eqtot;
    const unsigned d0 = s->pref_arr[1];
    bool compacted = false;

    if (E0 <= SVMAX) {
        // compact: top byte > d0 -> cand (order-free); == d0 -> surv
        for (int base = 0; base < NN; base += NT) {
            int i = base + tid;
            bool v = (i < NN);
            unsigned ok = v ? s->u.a.okey[i] : 0u;
            bool gt = v && ((ok >> 24) > d0);
            bool eq = v && ((ok >> 24) == d0);
            unsigned balg = __ballot_sync(0xffffffffu, gt);
            int pg = 0;
            if (lane == 0 && balg) pg = atomicAdd(&s->cntgt, __popc(balg));
            pg = __shfl_sync(0xffffffffu, pg, 0);
            if (gt) s->cand[pg + __popc(balg & ((1u << lane) - 1u))] =
                        (((unsigned long long)ok) << 32) | (unsigned)(~(unsigned)i);
            unsigned bale = __ballot_sync(0xffffffffu, eq);
            int pe = 0;
            if (lane == 0 && bale) pe = atomicAdd(&s->svcnt, __popc(bale));
            pe = __shfl_sync(0xffffffffu, pe, 0);
            if (eq) s->u.a.surv[pe + __popc(bale & ((1u << lane) - 1u))] =
                        (((unsigned long long)ok) << 32) | (unsigned)(~(unsigned)i);
        }
        __syncthreads();
        const int svn = s->svcnt;
        const int iters = (svn + NT - 1) / NT;

        // passes 1..3 over survivors
        for (int p = 1; p < 4; p++) {
            const int shift = 24 - 8 * p;
            if (tid < 256) s->u.a.hist256[tid] = 0u;
            __syncthreads();
            const unsigned prefv = s->pref_arr[p];
            const int krloc = s->kr_arr[p];
            for (int it = 0; it < iters; it++) {
                int ix = it * NT + tid;
                bool valid = (ix < svn);
                unsigned key = valid ? (unsigned)(s->u.a.surv[ix] >> 32) : 0u;
                bool part = valid && ((key >> (shift + 8)) == prefv);
                unsigned bucket = part ? ((key >> shift) & 255u) : 0xFFFFFFFFu;
                unsigned grp = __match_any_sync(0xffffffffu, bucket);
                if (part && lane == (__ffs(grp) - 1))
                    atomicAdd(&s->u.a.hist256[bucket], (unsigned)__popc(grp));
            }
            __syncthreads();
            unsigned cnt = 0, ssum = 0;
            if (tid < 256) {
                cnt = s->u.a.hist256[tid];
                ssum = cnt;
                #pragma unroll
                for (int d = 1; d < 32; d <<= 1) {
                    unsigned x = __shfl_down_sync(0xffffffffu, ssum, d);
                    if (lane + d < 32) ssum += x;
                }
                if (lane == 0) s->warpsum[wrp] = ssum;
            }
            __syncthreads();
            if (tid < 256) {
                unsigned hi = 0;
                for (int w = wrp + 1; w < 8; w++) hi += s->warpsum[w];
                unsigned S = ssum + hi;
                if (S >= (unsigned)krloc && S - cnt < (unsigned)krloc) {
                    s->pref_arr[p + 1] = (prefv << 8) | (unsigned)tid;
                    s->kr_arr[p + 1] = krloc - (int)(S - cnt);
                    s->eqtot = (int)cnt;
                }
            }
            __syncthreads();
        }

        if (s->eqtot == s->kr_arr[4]) {
            const unsigned T = s->pref_arr[4];
            for (int it = 0; it < iters; it++) {
                int ix = it * NT + tid;
                bool valid = (ix < svn);
                unsigned long long sv = valid ? s->u.a.surv[ix] : 0ull;
                bool take = valid && ((unsigned)(sv >> 32) >= T);
                unsigned bal = __ballot_sync(0xffffffffu, take);
                int pg = 0;
                if (lane == 0 && bal) pg = atomicAdd(&s->cntgt, __popc(bal));
                pg = __shfl_sync(0xffffffffu, pg, 0);
                if (take) s->cand[pg + __popc(bal & ((1u << lane) - 1u))] = sv;
            }
            compacted = true;
            __syncthreads();
        }
    } else {
        // full-scan passes 1..3
        for (int p = 1; p < 4; p++) {
            const int shift = 24 - 8 * p;
            for (int t = tid; t < 32 * HP; t += NT) s->u.a.hist32[t] = 0u;
            __syncthreads();
            const unsigned prefv = s->pref_arr[p];
            const int krloc = s->kr_arr[p];
            for (int base = 0; base < NN; base += NT) {
                int i = base + tid;
                bool v = (i < NN);
                unsigned ok = v ? s->u.a.okey[i] : 0u;
                bool part = v && ((ok >> (shift + 8)) == prefv);
                unsigned bucket = part ? ((ok >> shift) & 255u) : 0xFFFFFFFFu;
                unsigned grp = __match_any_sync(0xffffffffu, bucket);
                if (part && lane == (__ffs(grp) - 1))
                    s->u.a.hist32[wrp * HP + bucket] += (unsigned)__popc(grp);
            }
            __syncthreads();
            unsigned cnt = 0, ssum = 0;
            if (tid < 256) {
                #pragma unroll
                for (int w = 0; w < 32; w++) cnt += s->u.a.hist32[w * HP + tid];
                ssum = cnt;
                #pragma unroll
                for (int d = 1; d < 32; d <<= 1) {
                    unsigned x = __shfl_down_sync(0xffffffffu, ssum, d);
                    if (lane + d < 32) ssum += x;
                }
                if (lane == 0) s->warpsum[wrp] = ssum;
            }
            __syncthreads();
            if (tid < 256) {
                unsigned hi = 0;
                for (int w = wrp + 1; w < 8; w++) hi += s->warpsum[w];
                unsigned S = ssum + hi;
                if (S >= (unsigned)krloc && S - cnt < (unsigned)krloc) {
                    s->pref_arr[p + 1] = (prefv << 8) | (unsigned)tid;
                    s->kr_arr[p + 1] = krloc - (int)(S - cnt);
                    s->eqtot = (int)cnt;
                }
            }
            __syncthreads();
        }
        if (s->eqtot == s->kr_arr[4] && s->pref_arr[4] != 0u) {
            const unsigned T = s->pref_arr[4];
            if (tid == 0) s->cntgt = 0;
            __syncthreads();
            int mycnt = 0;
            for (int base = 0; base < NN; base += NT) {
                int i = base + tid;
                bool take = (i < NN) && (s->u.a.okey[i] >= T);
                mycnt += __popc(__ballot_sync(0xffffffffu, take));
            }
            int wb = 0;
            if (lane == 0) wb = atomicAdd(&s->cntgt, mycnt);
            wb = __shfl_sync(0xffffffffu, wb, 0);
            for (int base = 0; base < NN; base += NT) {
                int i = base + tid;
                bool take = (i < NN) && (s->u.a.okey[i] >= T);
                unsigned bal = __ballot_sync(0xffffffffu, take);
                if (take) {
                    int pos = wb + __popc(bal & ((1u << lane) - 1u));
                    s->cand[pos] = (((unsigned long long)s->u.a.okey[i]) << 32) | (unsigned)(~(unsigned)i);
                }
                wb += __popc(bal);
            }
            compacted = true;
            __syncthreads();
        }
    }

    // stable fallback (rare: ties beyond cutoff or T==0)
    if (!compacted) {
        const unsigned T = s->pref_arr[4];
        const int need = s->kr_arr[4];
        const int eq0 = KK - need;
        __syncthreads();
        if (tid == 0) s->cntgt = 0;
        __syncthreads();
        int eqbase = 0;
        for (int base = 0; base < NN; base += NT) {
            int i = base + tid;
            bool v = (i < NN);
            unsigned ok = v ? s->u.a.okey[i] : 0u;
            bool gt = v && (ok > T);
            bool eq = v && (ok == T);
            if (gt) {
                int p2 = atomicAdd(&s->cntgt, 1);
                s->cand[p2] = (((unsigned long long)ok) << 32) | (unsigned)(~(unsigned)i);
            }
            unsigned bal = __ballot_sync(0xffffffffu, eq);
            if (lane == 0) s->wsum[wrp] = __popc(bal);
            __syncthreads();
            int woff = 0, tot = 0;
            #pragma unroll
            for (int w = 0; w < 32; w++) { int x = s->wsum[w]; if (w < wrp) woff += x; tot += x; }
            int rank = eqbase + woff + __popc(bal & ((1u << lane) - 1u));
            if (eq && rank < need)
                s->cand[eq0 + rank] = (((unsigned long long)T) << 32) | (unsigned)(~(unsigned)i);
            eqbase += tot;
            __syncthreads();
        }
    }

    // ===== bitonic sort descending; warp-local shfl phases for j<=16 =====
    {
        unsigned long long v = s->cand[tid];
        #pragma unroll
        for (int k2 = 2; k2 <= 32; k2 <<= 1) {
            #pragma unroll
            for (int j = k2 >> 1; j >= 1; j >>= 1) {
                unsigned long long pv = __shfl_xor_sync(0xffffffffu, v, j);
                bool keepMax = ((tid & k2) == 0) == ((tid & j) == 0);
                v = keepMax ? (v > pv ? v : pv) : (v < pv ? v : pv);
            }
        }
        s->cand[tid] = v;
    }
    __syncthreads();
    for (int k2 = 64; k2 <= KK; k2 <<= 1) {
        for (int j = k2 >> 1; j >= 32; j >>= 1) {
            int ixj = tid ^ j;
            if (ixj > tid) {
                unsigned long long a = s->cand[tid], cc = s->cand[ixj];
                bool sw = ((tid & k2) == 0) ? (a < cc) : (a > cc);
                if (sw) { s->cand[tid] = cc; s->cand[ixj] = a; }
            }
            __syncthreads();
        }
        unsigned long long v = s->cand[tid];
        #pragma unroll
        for (int j = 16; j >= 1; j >>= 1) {
            unsigned long long pv = __shfl_xor_sync(0xffffffffu, v, j);
            bool keepMax = ((tid & k2) == 0) == ((tid & j) == 0);
            v = keepMax ? (v > pv ? v : pv) : (v < pv ? v : pv);
        }
        s->cand[tid] = v;
        __syncthreads();
    }

    // ================= gather + decode into smem (union .n) =================
    float4 bj; float aj, ajp;
    bool alive;
    {
        int t = tid;
        unsigned long long cd = s->cand[t];
        int idx = (int)(~(unsigned)cd);
        unsigned ok = (unsigned)(cd >> 32);
        float c = __uint_as_float(ok & 0x7FFFFFFFu);
        float vj = (ok != 0u) ? (1.0f / (1.0f + expf(-c))) : -1.0f;
        alive = (ok != 0u);
        float4 a = ((const float4*)anchors)[idx];
        float4 l = ((const float4*)p_loc)[(size_t)b * NN + idx];
        float cx = a.x + l.x * 0.1f * a.z;
        float cy = a.y + l.y * 0.1f * a.w;
        float w = a.z * expf(l.z * 0.2f);
        float h = a.w * expf(l.w * 0.2f);
        float x1 = cx - w * 0.5f, y1 = cy - h * 0.5f;
        float x2 = cx + w * 0.5f, y2 = cy + h * 0.5f;
        bj = make_float4(x1, y1, x2, y2);
        aj = fmaxf(x2 - x1, 0.0f) * fmaxf(y2 - y1, 0.0f);
        ajp = aj + 1e-9f;
        s->u.n.sbox[t] = bj;
        s->u.n.sarea[t] = aj;
        s->u.n.sval[t] = vj;
        const float2* lm2 = (const float2*)(p_landms + ((size_t)b * NN + idx) * 10);
        #pragma unroll
        for (int p2 = 0; p2 < 5; p2++) {
            float2 d = lm2[p2];
            s->u.n.skpt[t * 10 + 2 * p2]     = a.x + d.x * 0.1f * a.z;
            s->u.n.skpt[t * 10 + 2 * p2 + 1] = a.y + d.y * 0.1f * a.w;
        }
    }
    __syncthreads();

    // ================= Phase A: intra-chunk 64x64 suppression masks =================
    {
        int t64 = tid & 63, base = tid & ~63;
        unsigned long long m = 0ull;
        for (int j = t64 + 1; j < 64; j++) {
            float4 bq = s->u.n.sbox[base + j];
            float  aq = s->u.n.sarea[base + j];
            float lx = fmaxf(bj.x, bq.x);
            float ly = fmaxf(bj.y, bq.y);
            float rx = fminf(bj.z, bq.z);
            float ry = fminf(bj.w, bq.w);
            float ww = fmaxf(rx - lx, 0.0f);
            float hh = fmaxf(ry - ly, 0.0f);
            float inter = ww * hh;
            // note: iou_sup(inter=0, ...) is false, so no zero-intersection branch needed
            unsigned long long sup = iou_sup(inter, aj, aq, aq + 1e-9f) ? 1ull : 0ull;
            m |= sup << j;
        }
        s->u.n.smask[tid] = m;
    }
    __syncthreads();

    // ===== Phase B: pipelined scan/apply, nanosleep-backed waits =====
    // warp w (w>=1) applies for its rows (chunk w/2); warp 0 is the scanner.
    volatile int* vpub = &s->pub;
    volatile int* vready = s->ready;
    volatile unsigned* vsalive = s->salive;

    if (wrp == 0) {
        for (int c = 0; c < 16; c++) {
            int target = (c == 0) ? 1 : 2;
            while (vready[c] < target) __nanosleep(32);
            unsigned long long a;
            if (c == 0) {
                unsigned blo = __ballot_sync(0xffffffffu, alive);
                a = (unsigned long long)blo | ((unsigned long long)vsalive[1] << 32);
            } else {
                a = (unsigned long long)vsalive[2 * c]
                  | ((unsigned long long)vsalive[2 * c + 1] << 32);
            }
            unsigned long long dlo = s->u.n.smask[c * 64 + lane];
            unsigned long long dhi = s->u.n.smask[c * 64 + 32 + lane];
            unsigned long long kept = 0ull;
            while (a) {
                int t = __ffsll((long long)a) - 1;
                kept |= (1ull << t);
                unsigned long long mrow = (t < 32)
                    ? __shfl_sync(0xffffffffu, dlo, t)
                    : __shfl_sync(0xffffffffu, dhi, t - 32);
                a &= ~(mrow | (1ull << t));
            }
            if (lane == 0) {
                s->skept[c] = kept;
                __threadfence_block();
                *vpub = c + 1;
            }
            __syncwarp();
        }
    } else {
        const int cw = wrp >> 1;   // my chunk
        for (int j = 0; j < cw; j++) {
            if (__ballot_sync(0xffffffffu, alive) == 0u) break;
            while (*vpub <= j) __nanosleep(32);
            unsigned long long k = s->skept[j];
            while (k) {
                int t = __ffsll((long long)k) - 1;
                k &= k - 1;
                int pi = j * 64 + t;
                float4 bi = s->u.n.sbox[pi];
                float  ai = s->u.n.sarea[pi];
                if (alive) {
                    float lx = fmaxf(bi.x, bj.x);
                    float ly = fmaxf(bi.y, bj.y);
                    float rx = fminf(bi.z, bj.z);
                    float ry = fminf(bi.w, bj.w);
                    float ww = fmaxf(rx - lx, 0.0f);
                    float hh = fmaxf(ry - ly, 0.0f);
                    float inter = ww * hh;
                    if (iou_sup(inter, ai, aj, ajp)) alive = false;
                }
                if (__ballot_sync(0xffffffffu, alive) == 0u) break;
            }
        }
        unsigned bal = __ballot_sync(0xffffffffu, alive);
        if (lane == 0) {
            s->salive[wrp] = bal;
            __threadfence_block();
            atomicAdd(&s->ready[cw], 1);
        }
    }
    __syncthreads();

    // ===== masked output: [ltrb(4) | kpts(10) | score(1)] * keep, float4 stores =====
    float4* out4 = (float4*)(out + (size_t)b * KK * 15);
    for (int e4 = tid; e4 < (KK * 15) / 4; e4 += NT) {
        float r[4];
        #pragma unroll
        for (int q = 0; q < 4; q++) {
            int e = e4 * 4 + q;
            int row = e / 15;
            int c2 = e - row * 15;
            float m = ((s->skept[row >> 6] >> (row & 63)) & 1ull) ? 1.0f : 0.0f;
            float v;
            if (c2 < 4)       v = ((const float*)&s->u.n.sbox[row])[c2];
            else if (c2 < 14) v = s->u.n.skpt[row * 10 + (c2 - 4)];
            else              v = s->u.n.sval[row];
            r[q] = v * m;
        }
        out4[e4] = make_float4(r[0], r[1], r[2], r[3]);
    }
}

extern "C" void kernel_launch(void* const* d_in, const int* in_sizes, int n_in,
                              void* d_out, int out_size) {
    const float* p_loc    = (const float*)d_in[0];
    const float* p_conf   = (const float*)d_in[1];
    const float* p_landms = (const float*)d_in[2];
    const float* anchors  = (const float*)d_in[3];

    cudaFuncSetAttribute(k_fused, cudaFuncAttributeMaxDynamicSharedMemorySize, (int)sizeof(SF));
    k_fused<<<BB, NT, sizeof(SF)>>>(p_loc, p_conf, p_landms, anchors, (float*)d_out);
}

// round 17
// speedup vs baseline: 1.2804x; 1.0259x over previous
#include <cuda_runtime.h>
#include <math.h>

#define NN 16800
#define KK 1024
#define BB 64
#define NT 1024
#define HP 257
#define SVMAX 6144
#define C_HI 0.2321f
#define C_LO 0.2295f

struct SF {
    union {
        struct {                              // select phase
            unsigned okey[NN];                // 67200 B
            unsigned hist32[32 * HP];         // 32896 B
            unsigned long long surv[SVMAX];   // 49152 B
            unsigned hist256[256];
        } a;
        struct {                              // nms phase
            float4 sbox[KK];
            float2 sul[KK];                   // {0.2321*area, 0.2295*area}
            float  sarea[KK];
            float  sval[KK];
            unsigned long long smask[KK];     // intra-chunk row masks
            float  skpt[KK * 10];
        } n;
    } u;
    unsigned long long cand[KK];
    unsigned long long skept[16];
    unsigned salive[32];
    int ready[16];
    int pub;
    unsigned warpsum[8];
    unsigned pref_arr[5];
    int kr_arr[5];
    int wsum[32];
    int cntgt;
    int svcnt;
    int eqtot;
};

__global__ __launch_bounds__(NT, 1)
void k_fused(const float* __restrict__ p_loc,
             const float* __restrict__ p_conf,
             const float* __restrict__ p_landms,
             const float* __restrict__ anchors,
             float* __restrict__ out)
{
    extern __shared__ char raw[];
    SF* s = reinterpret_cast<SF*>(raw);
    const int b = blockIdx.x, tid = threadIdx.x;
    const int lane = tid & 31, wrp = tid >> 5;
    const float* conf = p_conf + (size_t)b * NN;

    if (tid == 0) { s->pref_arr[0] = 0u; s->kr_arr[0] = KK; s->cntgt = 0; s->svcnt = 0; s->eqtot = 0; s->pub = 0; }
    if (tid < 16) s->ready[tid] = 0;

    // ================= pass 0: 8-bit top byte, per-warp histograms =================
    for (int t = tid; t < 32 * HP; t += NT) s->u.a.hist32[t] = 0u;
    __syncthreads();
    for (int base = 0; base < NN; base += NT) {
        int i = base + tid;
        bool v = (i < NN);
        unsigned ok = 0u;
        if (v) {
            float c = conf[i];
            ok = (c >= 0.0f) ? (__float_as_uint(c) | 0x80000000u) : 0u;
            s->u.a.okey[i] = ok;
        }
        unsigned bucket = v ? (ok >> 24) : 0xFFFFFFFFu;
        unsigned grp = __match_any_sync(0xffffffffu, bucket);
        if (v && lane == (__ffs(grp) - 1))
            s->u.a.hist32[wrp * HP + bucket] += (unsigned)__popc(grp);
    }
    __syncthreads();
    {   // digit find (threads 0..255 own buckets)
        unsigned cnt = 0, ssum = 0;
        if (tid < 256) {
            #pragma unroll
            for (int w = 0; w < 32; w++) cnt += s->u.a.hist32[w * HP + tid];
            ssum = cnt;
            #pragma unroll
            for (int d = 1; d < 32; d <<= 1) {
                unsigned x = __shfl_down_sync(0xffffffffu, ssum, d);
                if (lane + d < 32) ssum += x;
            }
            if (lane == 0) s->warpsum[wrp] = ssum;
        }
        __syncthreads();
        if (tid < 256) {
            unsigned hi = 0;
            for (int w = wrp + 1; w < 8; w++) hi += s->warpsum[w];
            unsigned S = ssum + hi;
            if (S >= (unsigned)KK && S - cnt < (unsigned)KK) {
                s->pref_arr[1] = (unsigned)tid;
                s->kr_arr[1] = KK - (int)(S - cnt);
                s->eqtot = (int)cnt;
            }
        }
        __syncthreads();
    }

    const int E0 = s->eqtot;
    const int cg0 = KK - s->kr_arr[1];
    const unsigned d0 = s->pref_arr[1];
    bool compacted = false;

    if (E0 + cg0 <= SVMAX && d0 != 0u) {
        // unified compaction: top byte >= d0 -> surv (order-free; sort normalizes)
        for (int base = 0; base < NN; base += NT) {
            int i = base + tid;
            bool v = (i < NN);
            unsigned ok = v ? s->u.a.okey[i] : 0u;
            bool take = v && ((ok >> 24) >= d0);
            unsigned bal = __ballot_sync(0xffffffffu, take);
            int pe = 0;
            if (lane == 0 && bal) pe = atomicAdd(&s->svcnt, __popc(bal));
            pe = __shfl_sync(0xffffffffu, pe, 0);
            if (take) s->u.a.surv[pe + __popc(bal & ((1u << lane) - 1u))] =
                        (((unsigned long long)ok) << 32) | (unsigned)(~(unsigned)i);
        }
        __syncthreads();
        const int svn = s->svcnt;
        const int iters = (svn + NT - 1) / NT;

        // passes 1..3 over survivors (gt items auto-excluded by prefix mismatch)
        for (int p = 1; p < 4; p++) {
            const int shift = 24 - 8 * p;
            if (tid < 256) s->u.a.hist256[tid] = 0u;
            __syncthreads();
            const unsigned prefv = s->pref_arr[p];
            const int krloc = s->kr_arr[p];
            for (int it = 0; it < iters; it++) {
                int ix = it * NT + tid;
                bool valid = (ix < svn);
                unsigned key = valid ? (unsigned)(s->u.a.surv[ix] >> 32) : 0u;
                bool part = valid && ((key >> (shift + 8)) == prefv);
                unsigned bucket = part ? ((key >> shift) & 255u) : 0xFFFFFFFFu;
                unsigned grp = __match_any_sync(0xffffffffu, bucket);
                if (part && lane == (__ffs(grp) - 1))
                    atomicAdd(&s->u.a.hist256[bucket], (unsigned)__popc(grp));
            }
            __syncthreads();
            unsigned cnt = 0, ssum = 0;
            if (tid < 256) {
                cnt = s->u.a.hist256[tid];
                ssum = cnt;
                #pragma unroll
                for (int d = 1; d < 32; d <<= 1) {
                    unsigned x = __shfl_down_sync(0xffffffffu, ssum, d);
                    if (lane + d < 32) ssum += x;
                }
                if (lane == 0) s->warpsum[wrp] = ssum;
            }
            __syncthreads();
            if (tid < 256) {
                unsigned hi = 0;
                for (int w = wrp + 1; w < 8; w++) hi += s->warpsum[w];
                unsigned S = ssum + hi;
                if (S >= (unsigned)krloc && S - cnt < (unsigned)krloc) {
                    s->pref_arr[p + 1] = (prefv << 8) | (unsigned)tid;
                    s->kr_arr[p + 1] = krloc - (int)(S - cnt);
                    s->eqtot = (int)cnt;
                }
            }
            __syncthreads();
        }

        if (s->eqtot == s->kr_arr[4]) {
            const unsigned T = s->pref_arr[4];
            if (tid == 0) s->cntgt = 0;
            __syncthreads();
            for (int it = 0; it < iters; it++) {
                int ix = it * NT + tid;
                bool valid = (ix < svn);
                unsigned long long sv = valid ? s->u.a.surv[ix] : 0ull;
                bool take = valid && ((unsigned)(sv >> 32) >= T);
                unsigned bal = __ballot_sync(0xffffffffu, take);
                int pg = 0;
                if (lane == 0 && bal) pg = atomicAdd(&s->cntgt, __popc(bal));
                pg = __shfl_sync(0xffffffffu, pg, 0);
                if (take) s->cand[pg + __popc(bal & ((1u << lane) - 1u))] = sv;
            }
            compacted = true;
            __syncthreads();
        }
    } else {
        // full-scan passes 1..3
        for (int p = 1; p < 4; p++) {
            const int shift = 24 - 8 * p;
            for (int t = tid; t < 32 * HP; t += NT) s->u.a.hist32[t] = 0u;
            __syncthreads();
            const unsigned prefv = s->pref_arr[p];
            const int krloc = s->kr_arr[p];
            for (int base = 0; base < NN; base += NT) {
                int i = base + tid;
                bool v = (i < NN);
                unsigned ok = v ? s->u.a.okey[i] : 0u;
                bool part = v && ((ok >> (shift + 8)) == prefv);
                unsigned bucket = part ? ((ok >> shift) & 255u) : 0xFFFFFFFFu;
                unsigned grp = __match_any_sync(0xffffffffu, bucket);
                if (part && lane == (__ffs(grp) - 1))
                    s->u.a.hist32[wrp * HP + bucket] += (unsigned)__popc(grp);
            }
            __syncthreads();
            unsigned cnt = 0, ssum = 0;
            if (tid < 256) {
                #pragma unroll
                for (int w = 0; w < 32; w++) cnt += s->u.a.hist32[w * HP + tid];
                ssum = cnt;
                #pragma unroll
                for (int d = 1; d < 32; d <<= 1) {
                    unsigned x = __shfl_down_sync(0xffffffffu, ssum, d);
                    if (lane + d < 32) ssum += x;
                }
                if (lane == 0) s->warpsum[wrp] = ssum;
            }
            __syncthreads();
            if (tid < 256) {
                unsigned hi = 0;
                for (int w = wrp + 1; w < 8; w++) hi += s->warpsum[w];
                unsigned S = ssum + hi;
                if (S >= (unsigned)krloc && S - cnt < (unsigned)krloc) {
                    s->pref_arr[p + 1] = (prefv << 8) | (unsigned)tid;
                    s->kr_arr[p + 1] = krloc - (int)(S - cnt);
                    s->eqtot = (int)cnt;
                }
            }
            __syncthreads();
        }
        if (s->eqtot == s->kr_arr[4] && s->pref_arr[4] != 0u) {
            const unsigned T = s->pref_arr[4];
            if (tid == 0) s->cntgt = 0;
            __syncthreads();
            int mycnt = 0;
            for (int base = 0; base < NN; base += NT) {
                int i = base + tid;
                bool take = (i < NN) && (s->u.a.okey[i] >= T);
                mycnt += __popc(__ballot_sync(0xffffffffu, take));
            }
            int wb = 0;
            if (lane == 0) wb = atomicAdd(&s->cntgt, mycnt);
            wb = __shfl_sync(0xffffffffu, wb, 0);
            for (int base = 0; base < NN; base += NT) {
                int i = base + tid;
                bool take = (i < NN) && (s->u.a.okey[i] >= T);
                unsigned bal = __ballot_sync(0xffffffffu, take);
                if (take) {
                    int pos = wb + __popc(bal & ((1u << lane) - 1u));
                    s->cand[pos] = (((unsigned long long)s->u.a.okey[i]) << 32) | (unsigned)(~(unsigned)i);
                }
                wb += __popc(bal);
            }
            compacted = true;
            __syncthreads();
        }
    }

    // stable fallback (rare: ties beyond cutoff or T==0)
    if (!compacted) {
        const unsigned T = s->pref_arr[4];
        const int need = s->kr_arr[4];
        const int eq0 = KK - need;
        __syncthreads();
        if (tid == 0) s->cntgt = 0;
        __syncthreads();
        int eqbase = 0;
        for (int base = 0; base < NN; base += NT) {
            int i = base + tid;
            bool v = (i < NN);
            unsigned ok = v ? s->u.a.okey[i] : 0u;
            bool gt = v && (ok > T);
            bool eq = v && (ok == T);
            if (gt) {
                int p2 = atomicAdd(&s->cntgt, 1);
                s->cand[p2] = (((unsigned long long)ok) << 32) | (unsigned)(~(unsigned)i);
            }
            unsigned bal = __ballot_sync(0xffffffffu, eq);
            if (lane == 0) s->wsum[wrp] = __popc(bal);
            __syncthreads();
            int woff = 0, tot = 0;
            #pragma unroll
            for (int w = 0; w < 32; w++) { int x = s->wsum[w]; if (w < wrp) woff += x; tot += x; }
            int rank = eqbase + woff + __popc(bal & ((1u << lane) - 1u));
            if (eq && rank < need)
                s->cand[eq0 + rank] = (((unsigned long long)T) << 32) | (unsigned)(~(unsigned)i);
            eqbase += tot;
            __syncthreads();
        }
    }

    // ===== bitonic sort descending; warp-local shfl phases for j<=16 =====
    {
        unsigned long long v = s->cand[tid];
        #pragma unroll
        for (int k2 = 2; k2 <= 32; k2 <<= 1) {
            #pragma unroll
            for (int j = k2 >> 1; j >= 1; j >>= 1) {
                unsigned long long pv = __shfl_xor_sync(0xffffffffu, v, j);
                bool keepMax = ((tid & k2) == 0) == ((tid & j) == 0);
                v = keepMax ? (v > pv ? v : pv) : (v < pv ? v : pv);
            }
        }
        s->cand[tid] = v;
    }
    __syncthreads();
    for (int k2 = 64; k2 <= KK; k2 <<= 1) {
        for (int j = k2 >> 1; j >= 32; j >>= 1) {
            int ixj = tid ^ j;
            if (ixj > tid) {
                unsigned long long a = s->cand[tid], cc = s->cand[ixj];
                bool sw = ((tid & k2) == 0) ? (a < cc) : (a > cc);
                if (sw) { s->cand[tid] = cc; s->cand[ixj] = a; }
            }
            __syncthreads();
        }
        unsigned long long v = s->cand[tid];
        #pragma unroll
        for (int j = 16; j >= 1; j >>= 1) {
            unsigned long long pv = __shfl_xor_sync(0xffffffffu, v, j);
            bool keepMax = ((tid & k2) == 0) == ((tid & j) == 0);
            v = keepMax ? (v > pv ? v : pv) : (v < pv ? v : pv);
        }
        s->cand[tid] = v;
        __syncthreads();
    }

    // ================= gather + decode into smem (union .n) =================
    float4 bj; float aj, u_me, l_me;
    bool alive;
    {
        int t = tid;
        unsigned long long cd = s->cand[t];
        int idx = (int)(~(unsigned)cd);
        unsigned ok = (unsigned)(cd >> 32);
        float c = __uint_as_float(ok & 0x7FFFFFFFu);
        float vj = (ok != 0u) ? (1.0f / (1.0f + expf(-c))) : -1.0f;
        alive = (ok != 0u);
        float4 a = ((const float4*)anchors)[idx];
        float4 l = ((const float4*)p_loc)[(size_t)b * NN + idx];
        float cx = a.x + l.x * 0.1f * a.z;
        float cy = a.y + l.y * 0.1f * a.w;
        float w = a.z * expf(l.z * 0.2f);
        float h = a.w * expf(l.w * 0.2f);
        float x1 = cx - w * 0.5f, y1 = cy - h * 0.5f;
        float x2 = cx + w * 0.5f, y2 = cy + h * 0.5f;
        bj = make_float4(x1, y1, x2, y2);
        aj = fmaxf(x2 - x1, 0.0f) * fmaxf(y2 - y1, 0.0f);
        u_me = C_HI * aj;
        l_me = C_LO * aj;
        s->u.n.sbox[t] = bj;
        s->u.n.sul[t] = make_float2(u_me, l_me);
        s->u.n.sarea[t] = aj;
        s->u.n.sval[t] = vj;
        const float2* lm2 = (const float2*)(p_landms + ((size_t)b * NN + idx) * 10);
        #pragma unroll
        for (int p2 = 0; p2 < 5; p2++) {
            float2 d = lm2[p2];
            s->u.n.skpt[t * 10 + 2 * p2]     = a.x + d.x * 0.1f * a.z;
            s->u.n.skpt[t * 10 + 2 * p2 + 1] = a.y + d.y * 0.1f * a.w;
        }
    }
    __syncthreads();

    // ================= Phase A: intra-chunk 64x64 suppression masks =================
    // suppress iff iou>0.3; mul-form bands (u=C_HI*area, l=C_LO*area):
    //   inter > u_i+u_j  -> certainly iou>0.302 ; inter <= l_i+l_j -> certainly iou<0.298
    //   else exact reference-order divide. Decisions bit-identical.
    {
        int t64 = tid & 63, base = tid & ~63;
        unsigned long long m = 0ull;
        for (int j = t64 + 1; j < 64; j++) {
            float4 bq = s->u.n.sbox[base + j];
            float2 ul = s->u.n.sul[base + j];
            float lx = fmaxf(bj.x, bq.x);
            float ly = fmaxf(bj.y, bq.y);
            float rx = fminf(bj.z, bq.z);
            float ry = fminf(bj.w, bq.w);
            float ww = fmaxf(rx - lx, 0.0f);
            float hh = fmaxf(ry - ly, 0.0f);
            float inter = ww * hh;
            bool sup;
            if (inter > u_me + ul.x) sup = true;
            else if (inter > l_me + ul.y) {
                float dex = aj + s->u.n.sarea[base + j] - inter + 1e-9f;
                sup = __fdiv_rn(inter, dex) > 0.3f;
            } else sup = false;
            m |= (sup ? 1ull : 0ull) << j;
        }
        s->u.n.smask[tid] = m;
    }
    __syncthreads();

    // ===== Phase B: pipelined scan/apply + fused per-warp output =====
    volatile int* vpub = &s->pub;
    volatile int* vready = s->ready;
    volatile unsigned* vsalive = s->salive;
    const int cw = wrp >> 1;   // my chunk (rows 32*wrp..32*wrp+31 are in chunk wrp/2)

    if (wrp == 0) {
        for (int c = 0; c < 16; c++) {
            unsigned long long dlo = s->u.n.smask[c * 64 + lane];        // prefetch before wait
            unsigned long long dhi = s->u.n.smask[c * 64 + 32 + lane];
            int target = (c == 0) ? 1 : 2;
            while (vready[c] < target) __nanosleep(32);
            unsigned long long a;
            if (c == 0) {
                unsigned blo = __ballot_sync(0xffffffffu, alive);
                a = (unsigned long long)blo | ((unsigned long long)vsalive[1] << 32);
            } else {
                a = (unsigned long long)vsalive[2 * c]
                  | ((unsigned long long)vsalive[2 * c + 1] << 32);
            }
            unsigned long long kept = 0ull;
            while (a) {
                int t = __ffsll((long long)a) - 1;
                kept |= (1ull << t);
                unsigned long long mrow = (t < 32)
                    ? __shfl_sync(0xffffffffu, dlo, t)
                    : __shfl_sync(0xffffffffu, dhi, t - 32);
                a &= ~(mrow | (1ull << t));
            }
            if (lane == 0) {
                s->skept[c] = kept;
                __threadfence_block();
                *vpub = c + 1;
            }
            __syncwarp();
        }
    } else {
        for (int j = 0; j < cw; j++) {
            if (__ballot_sync(0xffffffffu, alive) == 0u) break;
            while (*vpub <= j) __nanosleep(32);
            unsigned long long k = s->skept[j];
            while (k) {
                int t = __ffsll((long long)k) - 1;
                k &= k - 1;
                int pi = j * 64 + t;
                float4 bi = s->u.n.sbox[pi];
                float2 ul = s->u.n.sul[pi];
                if (alive) {
                    float lx = fmaxf(bi.x, bj.x);
                    float ly = fmaxf(bi.y, bj.y);
                    float rx = fminf(bi.z, bj.z);
                    float ry = fminf(bi.w, bj.w);
                    float ww = fmaxf(rx - lx, 0.0f);
                    float hh = fmaxf(ry - ly, 0.0f);
                    float inter = ww * hh;
                    if (inter > u_me + ul.x) alive = false;
                    else if (inter > l_me + ul.y) {
                        float dex = s->u.n.sarea[pi] + aj - inter + 1e-9f;
                        if (__fdiv_rn(inter, dex) > 0.3f) alive = false;
                    }
                }
                if (__ballot_sync(0xffffffffu, alive) == 0u) break;
            }
        }
        unsigned bal = __ballot_sync(0xffffffffu, alive);
        if (lane == 0) {
            s->salive[wrp] = bal;
            __threadfence_block();
            atomicAdd(&s->ready[cw], 1);
        }
        // wait for my chunk's final kept set, then write my 32 rows
        while (*vpub <= cw) __nanosleep(32);
    }

    // ===== fused output: warp wrp owns rows 32*wrp..+31 -> floats [480*wrp, +480) =====
    {
        unsigned long long keepw = s->skept[cw];
        const int r0 = wrp * 32;
        float4* out4 = (float4*)(out + (size_t)b * KK * 15) + wrp * 120;
        for (int e4 = lane; e4 < 120; e4 += 32) {
            float r[4];
            #pragma unroll
            for (int q = 0; q < 4; q++) {
                int le = e4 * 4 + q;            // 0..479 within warp block
                int rr = le / 15;               // 0..31
                int c2 = le - rr * 15;
                int row = r0 + rr;
                float m = ((keepw >> (row & 63)) & 1ull) ? 1.0f : 0.0f;
                float v;
                if (c2 < 4)       v = ((const float*)&s->u.n.sbox[row])[c2];
                else if (c2 < 14) v = s->u.n.skpt[row * 10 + (c2 - 4)];
                else              v = s->u.n.sval[row];
                r[q] = v * m;
            }
            out4[e4] = make_float4(r[0], r[1], r[2], r[3]);
        }
    }
}

extern "C" void kernel_launch(void* const* d_in, const int* in_sizes, int n_in,
                              void* d_out, int out_size) {
    const float* p_loc    = (const float*)d_in[0];
    const float* p_conf   = (const float*)d_in[1];
    const float* p_landms = (const float*)d_in[2];
    const float* anchors  = (const float*)d_in[3];

    cudaFuncSetAttribute(k_fused, cudaFuncAttributeMaxDynamicSharedMemorySize, (int)sizeof(SF));
    k_fused<<<BB, NT, sizeof(SF)>>>(p_loc, p_conf, p_landms, anchors, (float*)d_out);
}